// round 12
// baseline (speedup 1.0000x reference)
#include <cuda_runtime.h>

// SpatialAwareFocalLoss — GB300 sm_103a, round 12.
// R11 base (grid=128 = 2 CTAs/seq × 4 classes, 1024 thr, two-array line bins,
// packed-u64 single-atomic finish) + Montgomery batch inversion: ONE RCP for
// all four sigmoids (Π(1+e_c) inverted once, per-class a_c rebuilt by FMULs).
// MUFU per thread: 13 -> 10 on the critical pre-barrier phase.

static constexpr int S    = 1024;   // SEQ_LEN
static constexpr int NBIN = 262;    // bin idx = line + 2, lines 0..255

__device__ unsigned long long g_word = 0ULL;   // [63:48]=count, [47:0]=sum*2^32

__global__ __launch_bounds__(1024, 1)
void focal_kernel(const float* __restrict__ pred,
                  const float* __restrict__ target,
                  const int*   __restrict__ token_to_line,
                  float* __restrict__ out,
                  float inv_total, int nblocks)
{
    __shared__ int   s_bin_i[NBIN];  // cnt + (tsum<<16)
    __shared__ float s_bin_f[NBIN];  // this half's sigmoid sum per line
    __shared__ float s_red[32];

    const int bid  = blockIdx.x;
    const int b    = bid >> 1;        // sequence
    const int half = bid & 1;         // classes 0-3 or 4-7
    const int i    = threadIdx.x;
    const int lane = i & 31, warp = i >> 5;

    const long tok  = (long)b * S + i;
    const long base = tok * 8;

    // all independent loads issued up front (li gates the atomic phase)
    const int    li = __ldg(token_to_line + tok);
    const float4 p4 = __ldg((const float4*)(pred + base + half * 4));
    const float4 ta = __ldg((const float4*)(target + base));
    const float4 tb = __ldg((const float4*)(target + base + 4));

    if (i < NBIN) { s_bin_i[i] = 0; s_bin_f[i] = 0.0f; }

    // full-class token target sum (small integer, exact) -> window gate
    const int tint = (int)(ta.x + ta.y + ta.z + ta.w + tb.x + tb.y + tb.z + tb.w);

    const float4 ts = half ? tb : ta;
    float p[4] = {p4.x, p4.y, p4.z, p4.w};
    float t[4] = {ts.x, ts.y, ts.z, ts.w};

    // e_c = exp(-|x_c|), d_c = 1 + e_c  (4x MUFU.EX2)
    float e[4], d[4];
    #pragma unroll
    for (int c = 0; c < 4; ++c) {
        e[c] = __expf(-fabsf(p[c]));
        d[c] = 1.0f + e[c];
    }
    // batch inversion: one RCP for all four 1/(1+e_c)
    const float m01 = d[0] * d[1];
    const float m23 = d[2] * d[3];
    const float r   = __fdividef(1.0f, m01 * m23);   // 1 MUFU.RCP
    float av[4];
    av[0] = d[1] * m23 * r;
    av[1] = d[0] * m23 * r;
    av[2] = m01 * d[3] * r;
    av[3] = m01 * d[2] * r;

    float sigsum = 0.0f, local = 0.0f;
    #pragma unroll
    for (int c = 0; c < 4; ++c) {
        const float x = p[c];
        const float a = av[c];                    // sigmoid(|x|)
        const float g = e[c] * a;                 // 1 - sigmoid(|x|)
        const float sig  = (x >= 0.0f) ? a : g;
        const float sig1 = (x >= 0.0f) ? g : a;   // 1 - sig
        sigsum += sig;
        const float pt  = (t[c] > 0.5f) ? sig : sig1;
        const float omp = (t[c] > 0.5f) ? sig1 : sig;   // 1 - pt
        const float bce = -__logf(pt);            // 1 MUFU.LG2
        const float o2  = omp * omp;
        local += 0.01f * o2 * o2 * bce;           // ALPHA*(1-pt)^GAMMA*bce
    }

    __syncthreads();                              // barrier 1: bins zeroed

    const int self_i = 1 + (tint << 16);
    atomicAdd(&s_bin_i[li + 2], self_i);
    atomicAdd(&s_bin_f[li + 2], sigsum);
    __syncthreads();                              // barrier 2: bins complete

    // window lines [li-2, li+2] -> bins [li, li+4]; exclude self
    int   ci   = -self_i;
    float nsig = -sigsum;
    #pragma unroll
    for (int k = 0; k < 5; ++k) {
        ci   += s_bin_i[li + k];
        nsig += s_bin_f[li + k];
    }
    const int cnt  = ci & 0xffff;                 // neighbors excluding self
    const int ntgt = ci >> 16;                    // exact integer gate

    if (cnt > 0 && ntgt > 0)
        local += 0.03f * __fdividef(nsig, (float)cnt);

    // block reduction
    #pragma unroll
    for (int o = 16; o > 0; o >>= 1)
        local += __shfl_xor_sync(0xffffffffu, local, o);
    if (lane == 0) s_red[warp] = local;
    __syncthreads();                              // barrier 3

    if (warp == 0) {
        float v = s_red[lane];
        #pragma unroll
        for (int o = 16; o > 0; o >>= 1)
            v += __shfl_xor_sync(0xffffffffu, v, o);

        if (lane == 0) {
            // v >= 0 always; fixed-point pack {count<<48 | sum*2^32}
            const unsigned long long fix =
                (unsigned long long)__double2ll_rn((double)v * 4294967296.0);
            const unsigned long long pack = (1ULL << 48) + fix;
            const unsigned long long old  = atomicAdd(&g_word, pack);

            if ((int)(old >> 48) == nblocks - 1) {      // last CTA
                const unsigned long long tot =
                    (old + pack) & ((1ULL << 48) - 1ULL);
                out[0] = (float)((double)tot *
                                 ((1.0 / 4294967296.0) * (double)inv_total));
                *((volatile unsigned long long*)&g_word) = 0ULL;  // replay-safe
            }
        }
    }
}

extern "C" void kernel_launch(void* const* d_in, const int* in_sizes, int n_in,
                              void* d_out, int out_size)
{
    const float* pred   = (const float*)d_in[0];
    const float* target = (const float*)d_in[1];
    const int*   lines  = (const int*)d_in[2];
    float* out = (float*)d_out;

    const int BS = in_sizes[2];
    const int B  = BS / S;
    const int nblocks = 2 * B;                    // 128 CTAs
    const float inv_total = 1.0f / ((float)BS * 8.0f);

    focal_kernel<<<nblocks, 1024>>>(pred, target, lines, out, inv_total, nblocks);
}

// round 13
// speedup vs baseline: 1.0625x; 1.0625x over previous
#include <cuda_runtime.h>

// SpatialAwareFocalLoss — GB300 sm_103a, round 13.
// R12 base + LG2 elimination: bce = log1p(e) [+ |x|], with log1p evaluated by
// the A&S 4.1.44 degree-8 minimax polynomial on the FMA pipe (|err|<=3e-8 on
// e in (0,1]). MUFU per thread: 10 -> 6 (4 EX2 + 2 RCP). XU pipe is the
// measured bottleneck (~200 cyc/MUFU on the critical path, R11->R12 data).

static constexpr int S    = 1024;   // SEQ_LEN
static constexpr int NBIN = 262;    // bin idx = line + 2, lines 0..255

__device__ unsigned long long g_word = 0ULL;   // [63:48]=count, [47:0]=sum*2^32

// ln(1+u), 0 <= u <= 1, Abramowitz & Stegun 4.1.44, |err| <= 3e-8
__device__ __forceinline__ float log1p_as(float u)
{
    float r = -0.0064535442f;
    r = fmaf(r, u,  0.0360884937f);
    r = fmaf(r, u, -0.0953293897f);
    r = fmaf(r, u,  0.1676540711f);
    r = fmaf(r, u, -0.2407338084f);
    r = fmaf(r, u,  0.3317990258f);
    r = fmaf(r, u, -0.4998741238f);
    r = fmaf(r, u,  0.9999964239f);
    return r * u;
}

__global__ __launch_bounds__(1024, 1)
void focal_kernel(const float* __restrict__ pred,
                  const float* __restrict__ target,
                  const int*   __restrict__ token_to_line,
                  float* __restrict__ out,
                  float inv_total, int nblocks)
{
    __shared__ int   s_bin_i[NBIN];  // cnt + (tsum<<16)
    __shared__ float s_bin_f[NBIN];  // this half's sigmoid sum per line
    __shared__ float s_red[32];

    const int bid  = blockIdx.x;
    const int b    = bid >> 1;        // sequence
    const int half = bid & 1;         // classes 0-3 or 4-7
    const int i    = threadIdx.x;
    const int lane = i & 31, warp = i >> 5;

    const long tok  = (long)b * S + i;
    const long base = tok * 8;

    // all independent loads issued up front (li gates the atomic phase)
    const int    li = __ldg(token_to_line + tok);
    const float4 p4 = __ldg((const float4*)(pred + base + half * 4));
    const float4 ta = __ldg((const float4*)(target + base));
    const float4 tb = __ldg((const float4*)(target + base + 4));

    if (i < NBIN) { s_bin_i[i] = 0; s_bin_f[i] = 0.0f; }

    // full-class token target sum (small integer, exact) -> window gate
    const int tint = (int)(ta.x + ta.y + ta.z + ta.w + tb.x + tb.y + tb.z + tb.w);

    const float4 ts = half ? tb : ta;
    float p[4] = {p4.x, p4.y, p4.z, p4.w};
    float t[4] = {ts.x, ts.y, ts.z, ts.w};

    // e_c = exp(-|x_c|) in (0,1], d_c = 1 + e_c  (4x MUFU.EX2)
    float e[4], d[4];
    #pragma unroll
    for (int c = 0; c < 4; ++c) {
        e[c] = __expf(-fabsf(p[c]));
        d[c] = 1.0f + e[c];
    }
    // batch inversion: ONE RCP for all four a_c = 1/(1+e_c)
    const float m01 = d[0] * d[1];
    const float m23 = d[2] * d[3];
    const float r   = __fdividef(1.0f, m01 * m23);   // 1 MUFU.RCP
    float av[4];
    av[0] = d[1] * m23 * r;
    av[1] = d[0] * m23 * r;
    av[2] = m01 * d[3] * r;
    av[3] = m01 * d[2] * r;

    float sigsum = 0.0f, local = 0.0f;
    #pragma unroll
    for (int c = 0; c < 4; ++c) {
        const float x  = p[c];
        const float a  = av[c];                   // sigmoid(|x|) = 1/d
        const float g  = e[c] * a;                // 1 - sigmoid(|x|)
        const bool  xp = (x >= 0.0f);
        const bool  tp = (t[c] > 0.5f);
        sigsum += xp ? a : g;                     // sigmoid(x)

        // pt is the g-branch iff (x>=0) XOR (t==1):
        //   t=1: pt=sig  -> g when x<0 ; t=0: pt=1-sig -> g when x>=0
        const bool  pg  = xp != tp;
        const float L   = log1p_as(e[c]);         // -log(a) = log(1+e)
        const float bce = pg ? (L + fabsf(x)) : L;  // -log(pt)
        const float omp = pg ? a : g;             // 1 - pt  (a+g == 1)
        const float o2  = omp * omp;
        local += 0.01f * o2 * o2 * bce;           // ALPHA*(1-pt)^GAMMA*bce
    }

    __syncthreads();                              // barrier 1: bins zeroed

    const int self_i = 1 + (tint << 16);
    atomicAdd(&s_bin_i[li + 2], self_i);
    atomicAdd(&s_bin_f[li + 2], sigsum);
    __syncthreads();                              // barrier 2: bins complete

    // window lines [li-2, li+2] -> bins [li, li+4]; exclude self
    int   ci   = -self_i;
    float nsig = -sigsum;
    #pragma unroll
    for (int k = 0; k < 5; ++k) {
        ci   += s_bin_i[li + k];
        nsig += s_bin_f[li + k];
    }
    const int cnt  = ci & 0xffff;                 // neighbors excluding self
    const int ntgt = ci >> 16;                    // exact integer gate

    if (cnt > 0 && ntgt > 0)
        local += 0.03f * __fdividef(nsig, (float)cnt);

    // block reduction
    #pragma unroll
    for (int o = 16; o > 0; o >>= 1)
        local += __shfl_xor_sync(0xffffffffu, local, o);
    if (lane == 0) s_red[warp] = local;
    __syncthreads();                              // barrier 3

    if (warp == 0) {
        float v = s_red[lane];
        #pragma unroll
        for (int o = 16; o > 0; o >>= 1)
            v += __shfl_xor_sync(0xffffffffu, v, o);

        if (lane == 0) {
            // v >= 0 always; fixed-point pack {count<<48 | sum*2^32}
            const unsigned long long fix =
                (unsigned long long)__double2ll_rn((double)v * 4294967296.0);
            const unsigned long long pack = (1ULL << 48) + fix;
            const unsigned long long old  = atomicAdd(&g_word, pack);

            if ((int)(old >> 48) == nblocks - 1) {      // last CTA
                const unsigned long long tot =
                    (old + pack) & ((1ULL << 48) - 1ULL);
                out[0] = (float)((double)tot *
                                 ((1.0 / 4294967296.0) * (double)inv_total));
                *((volatile unsigned long long*)&g_word) = 0ULL;  // replay-safe
            }
        }
    }
}

extern "C" void kernel_launch(void* const* d_in, const int* in_sizes, int n_in,
                              void* d_out, int out_size)
{
    const float* pred   = (const float*)d_in[0];
    const float* target = (const float*)d_in[1];
    const int*   lines  = (const int*)d_in[2];
    float* out = (float*)d_out;

    const int BS = in_sizes[2];
    const int B  = BS / S;
    const int nblocks = 2 * B;                    // 128 CTAs
    const float inv_total = 1.0f / ((float)BS * 8.0f);

    focal_kernel<<<nblocks, 1024>>>(pred, target, lines, out, inv_total, nblocks);
}